// round 14
// baseline (speedup 1.0000x reference)
#include <cuda_runtime.h>
#include <cstdint>

typedef unsigned long long ULL;

// ---------------- constants ----------------
constexpr int B  = 4;
constexpr int C  = 64;
constexpr int H  = 128;
constexpr int W  = 128;
constexpr int Hp = 130;
constexpr int Wp = 130;
constexpr int O  = 64;
constexpr int N9 = 9;

// prep kernel block ranges (pad/transpose + weight reshuffle only)
constexpr int NB_PAD = B * 529;                   // 2116 pad-transpose blocks
constexpr int NB_PW  = (O * C * N9 + 255) / 256;  // 144 weight blocks

// k_main smem layout (100 KB, 2 blocks/SM)
constexpr int SM_W     = 0;        // 32768 : [k][64 o] dup pairs (tap loop)
constexpr int SM_X     = 32768;    // 32768 : [64 c][128 px] 16B-chunk XOR swizzled
constexpr int SM_MIDX  = 65536;    // 18432 : int4  [9][128]
constexpr int SM_MW    = 83968;    // 18432 : float4[9][128]
constexpr int SM_MAIN  = 102400;
// prologue-only overlays (dead once tap loop starts):
constexpr int SM_WSM   = 0;        // 46080 : ULL [9][64][10] padded paired p_w
constexpr int SM_STASH = 46080;    //  9216 : ULL [128][9] partial sums

// ---------------- scratch (device globals; no allocs) ----------------
__device__ __align__(16) float g_xpad[B * Hp * Wp * C];   // NHWC zero-padded x0
__device__ __align__(16) ULL   g_wTn2[N9 * C * O];        // [n][c][o] -> (w, w) pair

// ---------------- packed f32x2 helpers ----------------
__device__ __forceinline__ ULL ffma2(ULL a, ULL b, ULL c) {
    ULL d;
    asm("fma.rn.f32x2 %0, %1, %2, %3;" : "=l"(d) : "l"(a), "l"(b), "l"(c));
    return d;
}
__device__ __forceinline__ ULL addf32x2(ULL a, ULL b) {
    ULL d;
    asm("add.rn.f32x2 %0, %1, %2;" : "=l"(d) : "l"(a), "l"(b));
    return d;
}
__device__ __forceinline__ ULL pack2(float lo, float hi) {
    ULL d;
    asm("mov.b64 %0, {%1, %2};" : "=l"(d) : "f"(lo), "f"(hi));
    return d;
}
__device__ __forceinline__ void unpack2(ULL v, float& lo, float& hi) {
    asm("mov.b64 {%0, %1}, %2;" : "=f"(lo), "=f"(hi) : "l"(v));
}

// ============================================================================
// k_prep: pad + NCHW->NHWC transpose of x0 | conv_w reshuffle. (No offset conv.)
// ============================================================================
__global__ void __launch_bounds__(256) k_prep(const float* __restrict__ x0,
                                              const float* __restrict__ conv_w) {
    __shared__ float tile[64][33];
    int t = threadIdx.x;
    int bid = blockIdx.x;

    if (bid < NB_PAD) {
        int b  = bid / 529;
        int p0 = (bid - b * 529) * 32;
        int tx = t & 31;
        int ty = t >> 5;

        #pragma unroll
        for (int cc = ty; cc < 64; cc += 8) {
            int p = p0 + tx;
            float v = 0.f;
            if (p < Hp * Wp) {
                int y = p / Wp, x = p - (p / Wp) * Wp;
                if (y >= 1 && y <= H && x >= 1 && x <= W)
                    v = x0[((b * C + cc) * H + (y - 1)) * W + (x - 1)];
            }
            tile[cc][tx] = v;
        }
        __syncthreads();

        int base = (b * Hp * Wp + p0) * 64;
        for (int e = t; e < 32 * 64; e += 256) {
            int pl = e >> 6, c = e & 63;
            if (p0 + pl < Hp * Wp)
                g_xpad[base + pl * 64 + c] = tile[c][pl];
        }
    } else {
        int idx = (bid - NB_PAD) * 256 + t;
        if (idx < O * C * N9) {
            int o = idx / (C * N9);
            int c = (idx / N9) % C;
            int n = idx % N9;
            float w = conv_w[idx];
            g_wTn2[(n * C + c) * O + o] = pack2(w, w);
        }
    }
}

// ============================================================================
// k_main: one row per block (128 px x 64 o), 256 threads, 2 blocks/SM.
// PROLOGUE: in-block offset conv (2 thr/px x 32 ch, smem-reduced) -> bilinear
// meta emitted into resident smem [9][128]. Then the proven R8 tap loop
// (stage W, gather, GEMM) with meta read straight from smem.
// ============================================================================
__global__ void __launch_bounds__(256, 2) k_main(const float* __restrict__ x1,
                                                 const float* __restrict__ p_w,
                                                 const float* __restrict__ p_b,
                                                 float* __restrict__ out) {
    extern __shared__ char dsm[];
    ULL*    ws2    = (ULL*)(dsm + SM_W);
    char*   xoffb  = dsm + SM_X;
    int4*   midx_s = (int4*)(dsm + SM_MIDX);    // [9][128]
    float4* mw_s   = (float4*)(dsm + SM_MW);    // [9][128]

    int t = threadIdx.x;
    int warp = t >> 5;
    int lane = t & 31;
    int bid = blockIdx.x;             // 512 blocks
    int i = bid & 127;
    int b = bid >> 7;

    // ================= PROLOGUE: offset conv + meta =================
    {
        ULL* wsm = (ULL*)(dsm + SM_WSM);        // [n*64+c][10] padded pairs
        for (int e = t; e < N9 * C * N9; e += 256) {
            int nc = e / 9, k = e - nc * 9;
            wsm[nc * 10 + k] = pack2(p_w[e], p_w[e + 5184]);
        }
        __syncthreads();

        int px  = t & 127;
        int half = t >> 7;
        int c0 = half << 5;

        ULL acc9[9];
        #pragma unroll
        for (int n = 0; n < 9; n++)
            acc9[n] = (half == 0) ? pack2(p_b[n], p_b[n + 9]) : 0ull;

        const float* x1b = x1 + ((b * C + c0) * H + i) * W + px;
        bool rok0 = (i > 0), rok2 = (i < H - 1);
        bool cok0 = (px > 0), cok2 = (px < W - 1);

        #pragma unroll 2
        for (int c = 0; c < 32; c++) {
            const float* xc = x1b + c * (H * W);
            float v[9];
            #pragma unroll
            for (int di = 0; di < 3; di++) {
                bool rok = (di == 0) ? rok0 : ((di == 2) ? rok2 : true);
                const float* xr = xc + (di - 1) * W;
                v[di * 3 + 0] = (rok && cok0) ? xr[-1] : 0.f;
                v[di * 3 + 1] = rok ? xr[0] : 0.f;
                v[di * 3 + 2] = (rok && cok2) ? xr[1] : 0.f;
            }
            ULL vd[9];
            #pragma unroll
            for (int k = 0; k < 9; k++) vd[k] = pack2(v[k], v[k]);
            #pragma unroll
            for (int n = 0; n < 9; n++) {
                const ULL* wn = wsm + (n * 64 + c0 + c) * 10;   // 80B-aligned row
                ulonglong2 wA = *(const ulonglong2*)(wn);
                ulonglong2 wB = *(const ulonglong2*)(wn + 2);
                ulonglong2 wC = *(const ulonglong2*)(wn + 4);
                ulonglong2 wD = *(const ulonglong2*)(wn + 6);
                ULL wE = wn[8];
                acc9[n] = ffma2(vd[0], wA.x, acc9[n]);
                acc9[n] = ffma2(vd[1], wA.y, acc9[n]);
                acc9[n] = ffma2(vd[2], wB.x, acc9[n]);
                acc9[n] = ffma2(vd[3], wB.y, acc9[n]);
                acc9[n] = ffma2(vd[4], wC.x, acc9[n]);
                acc9[n] = ffma2(vd[5], wC.y, acc9[n]);
                acc9[n] = ffma2(vd[6], wD.x, acc9[n]);
                acc9[n] = ffma2(vd[7], wD.y, acc9[n]);
                acc9[n] = ffma2(vd[8], wE,   acc9[n]);
            }
        }

        // reduce halves through smem, emit meta
        ULL* stash = (ULL*)(dsm + SM_STASH);
        if (half == 1) {
            #pragma unroll
            for (int n = 0; n < 9; n++) stash[px * 9 + n] = acc9[n];
        }
        __syncthreads();
        if (half == 0) {
            int xb130 = b * 130;
            #pragma unroll
            for (int n = 0; n < 9; n++) {
                ULL s = addf32x2(acc9[n], stash[px * 9 + n]);
                float ox, oy;
                unpack2(s, ox, oy);
                float pxf = (float)(i + n / 3) + ox;
                float pyf = (float)(px + n % 3) + oy;
                float fx = floorf(pxf), fy = floorf(pyf);
                int qltx = max(min((int)fx, Hp - 1), 0);
                int qlty = max(min((int)fy, Wp - 1), 0);
                int qrbx = max(min((int)fx + 1, Hp - 1), 0);
                int qrby = max(min((int)fy + 1, Wp - 1), 0);
                float pxc = fminf(fmaxf(pxf, 0.f), (float)(Hp - 1));
                float pyc = fminf(fmaxf(pyf, 0.f), (float)(Wp - 1));
                float ax = 1.f + (float)qltx - pxc;
                float bx = 1.f - (float)qrbx + pxc;
                float ay = 1.f + (float)qlty - pyc;
                float by = 1.f - (float)qrby + pyc;
                int4 idx;
                idx.x = ((xb130 + qltx) * 130 + qlty) * 64;
                idx.y = ((xb130 + qrbx) * 130 + qrby) * 64;
                idx.z = ((xb130 + qltx) * 130 + qrby) * 64;
                idx.w = ((xb130 + qrbx) * 130 + qlty) * 64;
                float4 wv;
                wv.x = ax * ay;
                wv.y = bx * by;
                wv.z = ax * by;
                wv.w = bx * ay;
                midx_s[n * 128 + px] = idx;
                mw_s[n * 128 + px]   = wv;
            }
        }
        __syncthreads();
    }

    // ================= TAP LOOP (R8 shape, meta from smem) =================
    int lg = t & 15;                  // gather: channel quad (c = lg*4)
    int hg = t >> 4;                  // gather: 8-px group
    int xorc = lg & 7;

    ULL acc[8][2];
    #pragma unroll
    for (int r = 0; r < 8; r++) { acc[r][0] = 0ull; acc[r][1] = 0ull; }

    const float* xb = g_xpad + lg * 4;

    #pragma unroll 1
    for (int n = 0; n < 9; n++) {
        // ---- phase 1: stage W(n), gather X(n) ----
        {
            const float4* wsrc = (const float4*)(g_wTn2 + n * 4096);
            float4* wdst = (float4*)(dsm + SM_W);
            #pragma unroll
            for (int k2 = 0; k2 < 8; k2++) wdst[t + k2 * 256] = wsrc[t + k2 * 256];
        }

        #pragma unroll 1
        for (int j = 0; j < 2; j++) {
            float rr[4][4];
            #pragma unroll
            for (int jj = 0; jj < 4; jj++) {
                int px = hg * 8 + j * 4 + jj;
                int4   id = midx_s[n * 128 + px];
                float4 g  = mw_s[n * 128 + px];
                float4 v0 = *(const float4*)(xb + id.x);
                float4 v1 = *(const float4*)(xb + id.y);
                float4 v2 = *(const float4*)(xb + id.z);
                float4 v3 = *(const float4*)(xb + id.w);
                rr[jj][0] = g.x * v0.x + g.y * v1.x + g.z * v2.x + g.w * v3.x;
                rr[jj][1] = g.x * v0.y + g.y * v1.y + g.z * v2.y + g.w * v3.y;
                rr[jj][2] = g.x * v0.z + g.y * v1.z + g.z * v2.z + g.w * v3.z;
                rr[jj][3] = g.x * v0.w + g.y * v1.w + g.z * v2.w + g.w * v3.w;
            }
            int chunk = (hg * 2 + j) ^ xorc;   // XOR-swizzled 16B chunk (4 px)
            #pragma unroll
            for (int q = 0; q < 4; q++) {
                *(float4*)(xoffb + ((lg * 4 + q) << 9) + (chunk << 4)) =
                    make_float4(rr[0][q], rr[1][q], rr[2][q], rr[3][q]);
            }
        }
        __syncthreads();

        // ---- phase 2: GEMM: acc[o=warp*8+r][px lane*4..+3] += w[o,k]*x[k,px] ----
        #pragma unroll 4
        for (int k = 0; k < 64; k++) {
            int xk = (k >> 2) & 7;
            ulonglong2 xA = *(const ulonglong2*)(xoffb + (k << 9) + ((lane ^ xk) << 4));
            const ULL* wr = ws2 + (k << 6) + (warp << 3);      // warp-uniform
            ulonglong2 w01 = *(const ulonglong2*)(wr + 0);
            ulonglong2 w23 = *(const ulonglong2*)(wr + 2);
            ulonglong2 w45 = *(const ulonglong2*)(wr + 4);
            ulonglong2 w67 = *(const ulonglong2*)(wr + 6);
            acc[0][0] = ffma2(xA.x, w01.x, acc[0][0]);
            acc[0][1] = ffma2(xA.y, w01.x, acc[0][1]);
            acc[1][0] = ffma2(xA.x, w01.y, acc[1][0]);
            acc[1][1] = ffma2(xA.y, w01.y, acc[1][1]);
            acc[2][0] = ffma2(xA.x, w23.x, acc[2][0]);
            acc[2][1] = ffma2(xA.y, w23.x, acc[2][1]);
            acc[3][0] = ffma2(xA.x, w23.y, acc[3][0]);
            acc[3][1] = ffma2(xA.y, w23.y, acc[3][1]);
            acc[4][0] = ffma2(xA.x, w45.x, acc[4][0]);
            acc[4][1] = ffma2(xA.y, w45.x, acc[4][1]);
            acc[5][0] = ffma2(xA.x, w45.y, acc[5][0]);
            acc[5][1] = ffma2(xA.y, w45.y, acc[5][1]);
            acc[6][0] = ffma2(xA.x, w67.x, acc[6][0]);
            acc[6][1] = ffma2(xA.y, w67.x, acc[6][1]);
            acc[7][0] = ffma2(xA.x, w67.y, acc[7][0]);
            acc[7][1] = ffma2(xA.y, w67.y, acc[7][1]);
        }
        __syncthreads();
    }

    // ---- write out: o = warp*8+r; px lane*4..+3 (coalesced) ----
    float* ob = out + ((b * O + warp * 8) * H + i) * W + lane * 4;
    #pragma unroll
    for (int r = 0; r < 8; r++) {
        float4 v;
        unpack2(acc[r][0], v.x, v.y);
        unpack2(acc[r][1], v.z, v.w);
        *(float4*)(ob + r * (H * W)) = v;
    }
}

// ============================================================================
extern "C" void kernel_launch(void* const* d_in, const int* in_sizes, int n_in,
                              void* d_out, int out_size) {
    const float* x0     = (const float*)d_in[0];
    const float* x1     = (const float*)d_in[1];
    const float* p_w    = (const float*)d_in[2];
    const float* p_b    = (const float*)d_in[3];
    const float* conv_w = (const float*)d_in[4];
    float* out = (float*)d_out;

    cudaFuncSetAttribute(k_main, cudaFuncAttributeMaxDynamicSharedMemorySize, SM_MAIN);

    k_prep<<<NB_PAD + NB_PW, 256>>>(x0, conv_w);
    k_main<<<B * H, 256, SM_MAIN>>>(x1, p_w, p_b, out);
}

// round 15
// speedup vs baseline: 1.4792x; 1.4792x over previous
#include <cuda_runtime.h>
#include <cstdint>

typedef unsigned long long ULL;

// ---------------- constants ----------------
constexpr int B  = 4;
constexpr int C  = 64;
constexpr int H  = 128;
constexpr int W  = 128;
constexpr int Hp = 130;
constexpr int Wp = 130;
constexpr int O  = 64;
constexpr int N9 = 9;
constexpr int BHW = B * H * W;   // 65536

// fused prep-kernel block ranges (R6 structure)
constexpr int NB_OFF = BHW / 256;                 // 256 offset-conv blocks
constexpr int NB_PAD = B * 529;                   // 2116 pad-transpose blocks
constexpr int NB_PW  = (O * C * N9 + 255) / 256;  // 144 weight blocks
constexpr int PREP_SMEM = N9 * C * 10 * 8;        // 46080 B (padded rows)

// k_main smem layout (R8: 72 KB total, 2 blocks/SM)
constexpr int SM_W    = 0;        // 32768 : [k][64 o] duplicated pairs
constexpr int SM_X    = 32768;    // 32768 : [64 c][128 px] 16B-chunk XOR swizzled
constexpr int SM_MIDX = 65536;    // 4096  : int4  [2][128]
constexpr int SM_MW   = 69632;    // 4096  : float4[2][128]
constexpr int SM_MAIN = 73728;

// ---------------- scratch (device globals; no allocs) ----------------
__device__ __align__(16) float g_xpad[B * Hp * Wp * C];   // NHWC zero-padded x0
__device__ __align__(16) ULL   g_wTn2[N9 * C * O];        // [n][c][o] -> (w, w) pair
__device__ __align__(16) int4   g_midx[N9 * BHW];         // [n][P] corner offsets
__device__ __align__(16) float4 g_mw[N9 * BHW];           // [n][P] bilinear weights

// ---------------- packed f32x2 helpers ----------------
__device__ __forceinline__ ULL ffma2(ULL a, ULL b, ULL c) {
    ULL d;
    asm("fma.rn.f32x2 %0, %1, %2, %3;" : "=l"(d) : "l"(a), "l"(b), "l"(c));
    return d;
}
__device__ __forceinline__ ULL pack2(float lo, float hi) {
    ULL d;
    asm("mov.b64 %0, {%1, %2};" : "=l"(d) : "f"(lo), "f"(hi));
    return d;
}
__device__ __forceinline__ void unpack2(ULL v, float& lo, float& hi) {
    asm("mov.b64 {%0, %1}, %2;" : "=f"(lo), "=f"(hi) : "l"(v));
}

// ============================================================================
// Fused prep kernel (R6 structure):
//  [0, NB_OFF)   offset conv + bilinear meta (padded 80B weight rows: 5 wide
//                LDS per (c,n) row instead of 9 scalar; FMA order unchanged)
//  [+NB_PAD)     pad + NCHW->NHWC transpose of x0
//  [+NB_PW)      conv_w -> duplicated-pair reshuffle
// ============================================================================
__global__ void __launch_bounds__(256) k_prep(const float* __restrict__ x0,
                                              const float* __restrict__ x1,
                                              const float* __restrict__ p_w,
                                              const float* __restrict__ p_b,
                                              const float* __restrict__ conv_w) {
    extern __shared__ char dsm[];
    int t = threadIdx.x;
    int bid = blockIdx.x;

    if (bid < NB_OFF) {
        // ---------------- offset conv + metadata ----------------
        ULL* wsm = (ULL*)dsm;   // [n*64+c][10] padded paired weights, 46080 B
        for (int e = t; e < N9 * C * N9; e += 256) {
            int nc = e / 9, k = e - nc * 9;
            wsm[nc * 10 + k] = pack2(p_w[e], p_w[e + 5184]);
        }
        __syncthreads();

        int P = bid * 256 + t;
        int b = P >> 14;
        int rem = P & 16383;
        int i = rem >> 7;
        int j = rem & 127;

        ULL acc[9];
        #pragma unroll
        for (int n = 0; n < 9; n++) acc[n] = pack2(p_b[n], p_b[n + 9]);

        const float* x1b = x1 + (b * C * H * W) + i * W + j;
        bool rok0 = (i > 0), rok2 = (i < H - 1), cok0 = (j > 0), cok2 = (j < W - 1);

        #pragma unroll 2
        for (int c = 0; c < C; c++) {
            const float* xc = x1b + c * (H * W);
            float v[9];
            #pragma unroll
            for (int di = 0; di < 3; di++) {
                bool rok = (di == 0) ? rok0 : ((di == 2) ? rok2 : true);
                const float* xr = xc + (di - 1) * W;
                v[di * 3 + 0] = (rok && cok0) ? xr[-1] : 0.f;
                v[di * 3 + 1] = rok ? xr[0] : 0.f;
                v[di * 3 + 2] = (rok && cok2) ? xr[1] : 0.f;
            }
            ULL vd[9];
            #pragma unroll
            for (int k = 0; k < 9; k++) vd[k] = pack2(v[k], v[k]);
            #pragma unroll
            for (int n = 0; n < 9; n++) {
                const ULL* wn = wsm + (n * 64 + c) * 10;   // 80B-aligned row
                ulonglong2 wA = *(const ulonglong2*)(wn);
                ulonglong2 wB = *(const ulonglong2*)(wn + 2);
                ulonglong2 wC = *(const ulonglong2*)(wn + 4);
                ulonglong2 wD = *(const ulonglong2*)(wn + 6);
                ULL wE = wn[8];
                acc[n] = ffma2(vd[0], wA.x, acc[n]);
                acc[n] = ffma2(vd[1], wA.y, acc[n]);
                acc[n] = ffma2(vd[2], wB.x, acc[n]);
                acc[n] = ffma2(vd[3], wB.y, acc[n]);
                acc[n] = ffma2(vd[4], wC.x, acc[n]);
                acc[n] = ffma2(vd[5], wC.y, acc[n]);
                acc[n] = ffma2(vd[6], wD.x, acc[n]);
                acc[n] = ffma2(vd[7], wD.y, acc[n]);
                acc[n] = ffma2(vd[8], wE,   acc[n]);
            }
        }

        int xb130 = b * 130;
        #pragma unroll
        for (int n = 0; n < 9; n++) {
            float ox, oy;
            unpack2(acc[n], ox, oy);
            float px = (float)(i + n / 3) + ox;
            float py = (float)(j + n % 3) + oy;
            float fx = floorf(px), fy = floorf(py);
            int qltx = max(min((int)fx, Hp - 1), 0);
            int qlty = max(min((int)fy, Wp - 1), 0);
            int qrbx = max(min((int)fx + 1, Hp - 1), 0);
            int qrby = max(min((int)fy + 1, Wp - 1), 0);
            float pxc = fminf(fmaxf(px, 0.f), (float)(Hp - 1));
            float pyc = fminf(fmaxf(py, 0.f), (float)(Wp - 1));
            float ax = 1.f + (float)qltx - pxc;
            float bx = 1.f - (float)qrbx + pxc;
            float ay = 1.f + (float)qlty - pyc;
            float by = 1.f - (float)qrby + pyc;
            int4 idx;
            idx.x = ((xb130 + qltx) * 130 + qlty) * 64;
            idx.y = ((xb130 + qrbx) * 130 + qrby) * 64;
            idx.z = ((xb130 + qltx) * 130 + qrby) * 64;
            idx.w = ((xb130 + qrbx) * 130 + qlty) * 64;
            float4 wv;
            wv.x = ax * ay;
            wv.y = bx * by;
            wv.z = ax * by;
            wv.w = bx * ay;
            g_midx[n * BHW + P] = idx;
            g_mw[n * BHW + P]   = wv;
        }
    } else if (bid < NB_OFF + NB_PAD) {
        // ---------------- pad + transpose ----------------
        float (*tile)[33] = (float(*)[33])dsm;
        int bp = bid - NB_OFF;
        int b  = bp / 529;
        int p0 = (bp - b * 529) * 32;
        int tx = t & 31;
        int ty = t >> 5;

        #pragma unroll
        for (int cc = ty; cc < 64; cc += 8) {
            int p = p0 + tx;
            float v = 0.f;
            if (p < Hp * Wp) {
                int y = p / Wp, x = p - (p / Wp) * Wp;
                if (y >= 1 && y <= H && x >= 1 && x <= W)
                    v = x0[((b * C + cc) * H + (y - 1)) * W + (x - 1)];
            }
            tile[cc][tx] = v;
        }
        __syncthreads();

        int base = (b * Hp * Wp + p0) * 64;
        for (int e = t; e < 32 * 64; e += 256) {
            int pl = e >> 6, c = e & 63;
            if (p0 + pl < Hp * Wp)
                g_xpad[base + pl * 64 + c] = tile[c][pl];
        }
    } else {
        // ---------------- conv_w reshuffle ----------------
        int idx = (bid - NB_OFF - NB_PAD) * 256 + t;
        if (idx < O * C * N9) {
            int o = idx / (C * N9);
            int c = (idx / N9) % C;
            int n = idx % N9;
            float w = conv_w[idx];
            g_wTn2[(n * C + c) * O + o] = pack2(w, w);
        }
    }
}

// ============================================================================
// k_main: 1-row blocks (128 px x 64 o), 256 threads, grid 512, smem-staged
// double-buffered meta, tap-major gather + broadcast-W GEMM.  (R8 verbatim —
// best measured variant, 174.0 us.)
// ============================================================================
__global__ void __launch_bounds__(256, 2) k_main(float* __restrict__ out) {
    extern __shared__ char dsm[];
    ULL*    ws2    = (ULL*)(dsm + SM_W);
    char*   xoffb  = dsm + SM_X;
    int4*   midx_s = (int4*)(dsm + SM_MIDX);    // [2][128]
    float4* mw_s   = (float4*)(dsm + SM_MW);    // [2][128]

    int t = threadIdx.x;
    int warp = t >> 5;
    int lane = t & 31;
    int bid = blockIdx.x;             // 512 blocks
    int i = bid & 127;
    int b = bid >> 7;
    int pixbase = (b * H + i) * W;

    int lg = t & 15;                  // gather: channel quad (c = lg*4)
    int hg = t >> 4;                  // gather: 8-px group (px = hg*8..+7)
    int xorc = lg & 7;

    ULL acc[8][2];
    #pragma unroll
    for (int r = 0; r < 8; r++) { acc[r][0] = 0ull; acc[r][1] = 0ull; }

    const float* xb = g_xpad + lg * 4;

    // prologue: stage meta(0) into buffer 0 (half threads idx, half weights)
    if (t < 128) midx_s[t] = g_midx[pixbase + t];
    else         mw_s[t - 128] = g_mw[pixbase + (t - 128)];
    __syncthreads();

    #pragma unroll 1
    for (int n = 0; n < 9; n++) {
        int cur = n & 1, nxt = cur ^ 1;

        // ---- phase 1: stage W(n), prefetch meta(n+1), gather X(n) ----
        {
            const float4* wsrc = (const float4*)(g_wTn2 + n * 4096);
            float4* wdst = (float4*)(dsm + SM_W);
            #pragma unroll
            for (int k2 = 0; k2 < 8; k2++) wdst[t + k2 * 256] = wsrc[t + k2 * 256];
        }
        if (n < 8) {
            if (t < 128) midx_s[nxt * 128 + t] = g_midx[(n + 1) * BHW + pixbase + t];
            else         mw_s[nxt * 128 + (t - 128)] = g_mw[(n + 1) * BHW + pixbase + (t - 128)];
        }

        #pragma unroll 1
        for (int j = 0; j < 2; j++) {
            float rr[4][4];
            #pragma unroll
            for (int jj = 0; jj < 4; jj++) {
                int px = hg * 8 + j * 4 + jj;
                int4   id = midx_s[cur * 128 + px];
                float4 g  = mw_s[cur * 128 + px];
                float4 v0 = *(const float4*)(xb + id.x);
                float4 v1 = *(const float4*)(xb + id.y);
                float4 v2 = *(const float4*)(xb + id.z);
                float4 v3 = *(const float4*)(xb + id.w);
                rr[jj][0] = g.x * v0.x + g.y * v1.x + g.z * v2.x + g.w * v3.x;
                rr[jj][1] = g.x * v0.y + g.y * v1.y + g.z * v2.y + g.w * v3.y;
                rr[jj][2] = g.x * v0.z + g.y * v1.z + g.z * v2.z + g.w * v3.z;
                rr[jj][3] = g.x * v0.w + g.y * v1.w + g.z * v2.w + g.w * v3.w;
            }
            int chunk = (hg * 2 + j) ^ xorc;   // XOR-swizzled 16B chunk (4 px)
            #pragma unroll
            for (int q = 0; q < 4; q++) {
                *(float4*)(xoffb + ((lg * 4 + q) << 9) + (chunk << 4)) =
                    make_float4(rr[0][q], rr[1][q], rr[2][q], rr[3][q]);
            }
        }
        __syncthreads();

        // ---- phase 2: GEMM: acc[o=warp*8+r][px lane*4..+3] += w[o,k]*x[k,px] ----
        #pragma unroll 4
        for (int k = 0; k < 64; k++) {
            int xk = (k >> 2) & 7;
            ulonglong2 xA = *(const ulonglong2*)(xoffb + (k << 9) + ((lane ^ xk) << 4));
            const ULL* wr = ws2 + (k << 6) + (warp << 3);      // warp-uniform
            ulonglong2 w01 = *(const ulonglong2*)(wr + 0);
            ulonglong2 w23 = *(const ulonglong2*)(wr + 2);
            ulonglong2 w45 = *(const ulonglong2*)(wr + 4);
            ulonglong2 w67 = *(const ulonglong2*)(wr + 6);
            acc[0][0] = ffma2(xA.x, w01.x, acc[0][0]);
            acc[0][1] = ffma2(xA.y, w01.x, acc[0][1]);
            acc[1][0] = ffma2(xA.x, w01.y, acc[1][0]);
            acc[1][1] = ffma2(xA.y, w01.y, acc[1][1]);
            acc[2][0] = ffma2(xA.x, w23.x, acc[2][0]);
            acc[2][1] = ffma2(xA.y, w23.x, acc[2][1]);
            acc[3][0] = ffma2(xA.x, w23.y, acc[3][0]);
            acc[3][1] = ffma2(xA.y, w23.y, acc[3][1]);
            acc[4][0] = ffma2(xA.x, w45.x, acc[4][0]);
            acc[4][1] = ffma2(xA.y, w45.x, acc[4][1]);
            acc[5][0] = ffma2(xA.x, w45.y, acc[5][0]);
            acc[5][1] = ffma2(xA.y, w45.y, acc[5][1]);
            acc[6][0] = ffma2(xA.x, w67.x, acc[6][0]);
            acc[6][1] = ffma2(xA.y, w67.x, acc[6][1]);
            acc[7][0] = ffma2(xA.x, w67.y, acc[7][0]);
            acc[7][1] = ffma2(xA.y, w67.y, acc[7][1]);
        }
        __syncthreads();
    }

    // ---- write out: o = warp*8+r; px lane*4..+3 (coalesced) ----
    float* ob = out + ((b * O + warp * 8) * H + i) * W + lane * 4;
    #pragma unroll
    for (int r = 0; r < 8; r++) {
        float4 v;
        unpack2(acc[r][0], v.x, v.y);
        unpack2(acc[r][1], v.z, v.w);
        *(float4*)(ob + r * (H * W)) = v;
    }
}

// ============================================================================
extern "C" void kernel_launch(void* const* d_in, const int* in_sizes, int n_in,
                              void* d_out, int out_size) {
    const float* x0     = (const float*)d_in[0];
    const float* x1     = (const float*)d_in[1];
    const float* p_w    = (const float*)d_in[2];
    const float* p_b    = (const float*)d_in[3];
    const float* conv_w = (const float*)d_in[4];
    float* out = (float*)d_out;

    cudaFuncSetAttribute(k_main, cudaFuncAttributeMaxDynamicSharedMemorySize, SM_MAIN);
    cudaFuncSetAttribute(k_prep, cudaFuncAttributeMaxDynamicSharedMemorySize, PREP_SMEM);

    k_prep<<<NB_OFF + NB_PAD + NB_PW, 256, PREP_SMEM>>>(x0, x1, p_w, p_b, conv_w);
    k_main<<<B * H, 256, SM_MAIN>>>(out);
}

// round 16
// speedup vs baseline: 1.6244x; 1.0982x over previous
#include <cuda_runtime.h>
#include <cstdint>

typedef unsigned long long ULL;

// ---------------- constants ----------------
constexpr int B  = 4;
constexpr int C  = 64;
constexpr int H  = 128;
constexpr int W  = 128;
constexpr int Hp = 130;
constexpr int Wp = 130;
constexpr int O  = 64;
constexpr int N9 = 9;
constexpr int BHW = B * H * W;   // 65536

// fused prep-kernel block ranges
constexpr int NB_OFF = BHW / 128;                 // 512 offset-conv blocks (128 px, c-split)
constexpr int NB_PAD = B * 529;                   // 2116 pad-transpose blocks
constexpr int NB_PW  = (O * C * N9 + 255) / 256;  // 144 weight blocks
constexpr int PREP_WSM   = N9 * C * 10 * 8;       // 46080 : padded paired p_w
constexpr int PREP_STASH = PREP_WSM;              // +9216 : ULL [128][9] partials
constexpr int PREP_SMEM  = PREP_WSM + 128 * 9 * 8;  // 55296 B

// k_main smem layout (R8: 72 KB total, 2 blocks/SM)
constexpr int SM_W    = 0;        // 32768 : [k][64 o] duplicated pairs
constexpr int SM_X    = 32768;    // 32768 : [64 c][128 px] 16B-chunk XOR swizzled
constexpr int SM_MIDX = 65536;    // 4096  : int4  [2][128]
constexpr int SM_MW   = 69632;    // 4096  : float4[2][128]
constexpr int SM_MAIN = 73728;

// ---------------- scratch (device globals; no allocs) ----------------
__device__ __align__(16) float g_xpad[B * Hp * Wp * C];   // NHWC zero-padded x0
__device__ __align__(16) ULL   g_wTn2[N9 * C * O];        // [n][c][o] -> (w, w) pair
__device__ __align__(16) int4   g_midx[N9 * BHW];         // [n][P] corner offsets
__device__ __align__(16) float4 g_mw[N9 * BHW];           // [n][P] bilinear weights

// ---------------- packed f32x2 helpers ----------------
__device__ __forceinline__ ULL ffma2(ULL a, ULL b, ULL c) {
    ULL d;
    asm("fma.rn.f32x2 %0, %1, %2, %3;" : "=l"(d) : "l"(a), "l"(b), "l"(c));
    return d;
}
__device__ __forceinline__ ULL addf32x2(ULL a, ULL b) {
    ULL d;
    asm("add.rn.f32x2 %0, %1, %2;" : "=l"(d) : "l"(a), "l"(b));
    return d;
}
__device__ __forceinline__ ULL pack2(float lo, float hi) {
    ULL d;
    asm("mov.b64 %0, {%1, %2};" : "=l"(d) : "f"(lo), "f"(hi));
    return d;
}
__device__ __forceinline__ void unpack2(ULL v, float& lo, float& hi) {
    asm("mov.b64 {%0, %1}, %2;" : "=f"(lo), "=f"(hi) : "l"(v));
}

// ============================================================================
// Fused prep kernel:
//  [0, NB_OFF)   offset conv + bilinear meta: 512 blocks x 128 px, 2 thr/px
//                with 32/32 channel split reduced through smem (halved block
//                latency -> fine-grained wave packing with transpose blocks)
//  [+NB_PAD)     pad + NCHW->NHWC transpose of x0
//  [+NB_PW)      conv_w -> duplicated-pair reshuffle
// ============================================================================
__global__ void __launch_bounds__(256) k_prep(const float* __restrict__ x0,
                                              const float* __restrict__ x1,
                                              const float* __restrict__ p_w,
                                              const float* __restrict__ p_b,
                                              const float* __restrict__ conv_w) {
    extern __shared__ char dsm[];
    int t = threadIdx.x;
    int bid = blockIdx.x;

    if (bid < NB_OFF) {
        // ---------------- offset conv + metadata ----------------
        ULL* wsm = (ULL*)dsm;   // [n*64+c][10] padded paired weights, 46080 B
        for (int e = t; e < N9 * C * N9; e += 256) {
            int nc = e / 9, k = e - nc * 9;
            wsm[nc * 10 + k] = pack2(p_w[e], p_w[e + 5184]);
        }
        __syncthreads();

        int i = bid & 127;                // row
        int b = bid >> 7;                 // batch
        int px = t & 127;                 // column j
        int half = t >> 7;                // channel half
        int c0 = half << 5;
        int P = ((b * H + i) << 7) + px;  // global pixel index

        ULL acc[9];
        #pragma unroll
        for (int n = 0; n < 9; n++)
            acc[n] = (half == 0) ? pack2(p_b[n], p_b[n + 9]) : 0ull;

        const float* x1b = x1 + ((b * C + c0) * H + i) * W + px;
        bool rok0 = (i > 0), rok2 = (i < H - 1);
        bool cok0 = (px > 0), cok2 = (px < W - 1);

        #pragma unroll 2
        for (int c = 0; c < 32; c++) {
            const float* xc = x1b + c * (H * W);
            float v[9];
            #pragma unroll
            for (int di = 0; di < 3; di++) {
                bool rok = (di == 0) ? rok0 : ((di == 2) ? rok2 : true);
                const float* xr = xc + (di - 1) * W;
                v[di * 3 + 0] = (rok && cok0) ? xr[-1] : 0.f;
                v[di * 3 + 1] = rok ? xr[0] : 0.f;
                v[di * 3 + 2] = (rok && cok2) ? xr[1] : 0.f;
            }
            ULL vd[9];
            #pragma unroll
            for (int k = 0; k < 9; k++) vd[k] = pack2(v[k], v[k]);
            #pragma unroll
            for (int n = 0; n < 9; n++) {
                const ULL* wn = wsm + (n * 64 + c0 + c) * 10;   // 80B-aligned row
                ulonglong2 wA = *(const ulonglong2*)(wn);
                ulonglong2 wB = *(const ulonglong2*)(wn + 2);
                ulonglong2 wC = *(const ulonglong2*)(wn + 4);
                ulonglong2 wD = *(const ulonglong2*)(wn + 6);
                ULL wE = wn[8];
                acc[n] = ffma2(vd[0], wA.x, acc[n]);
                acc[n] = ffma2(vd[1], wA.y, acc[n]);
                acc[n] = ffma2(vd[2], wB.x, acc[n]);
                acc[n] = ffma2(vd[3], wB.y, acc[n]);
                acc[n] = ffma2(vd[4], wC.x, acc[n]);
                acc[n] = ffma2(vd[5], wC.y, acc[n]);
                acc[n] = ffma2(vd[6], wD.x, acc[n]);
                acc[n] = ffma2(vd[7], wD.y, acc[n]);
                acc[n] = ffma2(vd[8], wE,   acc[n]);
            }
        }

        // reduce halves through smem; half 0 emits meta
        ULL* stash = (ULL*)(dsm + PREP_STASH);
        if (half == 1) {
            #pragma unroll
            for (int n = 0; n < 9; n++) stash[px * 9 + n] = acc[n];
        }
        __syncthreads();
        if (half == 0) {
            int xb130 = b * 130;
            #pragma unroll
            for (int n = 0; n < 9; n++) {
                ULL s = addf32x2(acc[n], stash[px * 9 + n]);
                float ox, oy;
                unpack2(s, ox, oy);
                float pxf = (float)(i + n / 3) + ox;
                float pyf = (float)(px + n % 3) + oy;
                float fx = floorf(pxf), fy = floorf(pyf);
                int qltx = max(min((int)fx, Hp - 1), 0);
                int qlty = max(min((int)fy, Wp - 1), 0);
                int qrbx = max(min((int)fx + 1, Hp - 1), 0);
                int qrby = max(min((int)fy + 1, Wp - 1), 0);
                float pxc = fminf(fmaxf(pxf, 0.f), (float)(Hp - 1));
                float pyc = fminf(fmaxf(pyf, 0.f), (float)(Wp - 1));
                float ax = 1.f + (float)qltx - pxc;
                float bx = 1.f - (float)qrbx + pxc;
                float ay = 1.f + (float)qlty - pyc;
                float by = 1.f - (float)qrby + pyc;
                int4 idx;
                idx.x = ((xb130 + qltx) * 130 + qlty) * 64;
                idx.y = ((xb130 + qrbx) * 130 + qrby) * 64;
                idx.z = ((xb130 + qltx) * 130 + qrby) * 64;
                idx.w = ((xb130 + qrbx) * 130 + qlty) * 64;
                float4 wv;
                wv.x = ax * ay;
                wv.y = bx * by;
                wv.z = ax * by;
                wv.w = bx * ay;
                g_midx[n * BHW + P] = idx;
                g_mw[n * BHW + P]   = wv;
            }
        }
    } else if (bid < NB_OFF + NB_PAD) {
        // ---------------- pad + transpose ----------------
        float (*tile)[33] = (float(*)[33])dsm;
        int bp = bid - NB_OFF;
        int b  = bp / 529;
        int p0 = (bp - b * 529) * 32;
        int tx = t & 31;
        int ty = t >> 5;

        #pragma unroll
        for (int cc = ty; cc < 64; cc += 8) {
            int p = p0 + tx;
            float v = 0.f;
            if (p < Hp * Wp) {
                int y = p / Wp, x = p - (p / Wp) * Wp;
                if (y >= 1 && y <= H && x >= 1 && x <= W)
                    v = x0[((b * C + cc) * H + (y - 1)) * W + (x - 1)];
            }
            tile[cc][tx] = v;
        }
        __syncthreads();

        int base = (b * Hp * Wp + p0) * 64;
        for (int e = t; e < 32 * 64; e += 256) {
            int pl = e >> 6, c = e & 63;
            if (p0 + pl < Hp * Wp)
                g_xpad[base + pl * 64 + c] = tile[c][pl];
        }
    } else {
        // ---------------- conv_w reshuffle ----------------
        int idx = (bid - NB_OFF - NB_PAD) * 256 + t;
        if (idx < O * C * N9) {
            int o = idx / (C * N9);
            int c = (idx / N9) % C;
            int n = idx % N9;
            float w = conv_w[idx];
            g_wTn2[(n * C + c) * O + o] = pack2(w, w);
        }
    }
}

// ============================================================================
// k_main: 1-row blocks (128 px x 64 o), 256 threads, grid 512, smem-staged
// double-buffered meta, tap-major gather + broadcast-W GEMM.  (R8 verbatim —
// best measured variant, 174.0-174.8 us across four runs. DO NOT TOUCH.)
// ============================================================================
__global__ void __launch_bounds__(256, 2) k_main(float* __restrict__ out) {
    extern __shared__ char dsm[];
    ULL*    ws2    = (ULL*)(dsm + SM_W);
    char*   xoffb  = dsm + SM_X;
    int4*   midx_s = (int4*)(dsm + SM_MIDX);    // [2][128]
    float4* mw_s   = (float4*)(dsm + SM_MW);    // [2][128]

    int t = threadIdx.x;
    int warp = t >> 5;
    int lane = t & 31;
    int bid = blockIdx.x;             // 512 blocks
    int i = bid & 127;
    int b = bid >> 7;
    int pixbase = (b * H + i) * W;

    int lg = t & 15;                  // gather: channel quad (c = lg*4)
    int hg = t >> 4;                  // gather: 8-px group (px = hg*8..+7)
    int xorc = lg & 7;

    ULL acc[8][2];
    #pragma unroll
    for (int r = 0; r < 8; r++) { acc[r][0] = 0ull; acc[r][1] = 0ull; }

    const float* xb = g_xpad + lg * 4;

    // prologue: stage meta(0) into buffer 0 (half threads idx, half weights)
    if (t < 128) midx_s[t] = g_midx[pixbase + t];
    else         mw_s[t - 128] = g_mw[pixbase + (t - 128)];
    __syncthreads();

    #pragma unroll 1
    for (int n = 0; n < 9; n++) {
        int cur = n & 1, nxt = cur ^ 1;

        // ---- phase 1: stage W(n), prefetch meta(n+1), gather X(n) ----
        {
            const float4* wsrc = (const float4*)(g_wTn2 + n * 4096);
            float4* wdst = (float4*)(dsm + SM_W);
            #pragma unroll
            for (int k2 = 0; k2 < 8; k2++) wdst[t + k2 * 256] = wsrc[t + k2 * 256];
        }
        if (n < 8) {
            if (t < 128) midx_s[nxt * 128 + t] = g_midx[(n + 1) * BHW + pixbase + t];
            else         mw_s[nxt * 128 + (t - 128)] = g_mw[(n + 1) * BHW + pixbase + (t - 128)];
        }

        #pragma unroll 1
        for (int j = 0; j < 2; j++) {
            float rr[4][4];
            #pragma unroll
            for (int jj = 0; jj < 4; jj++) {
                int px = hg * 8 + j * 4 + jj;
                int4   id = midx_s[cur * 128 + px];
                float4 g  = mw_s[cur * 128 + px];
                float4 v0 = *(const float4*)(xb + id.x);
                float4 v1 = *(const float4*)(xb + id.y);
                float4 v2 = *(const float4*)(xb + id.z);
                float4 v3 = *(const float4*)(xb + id.w);
                rr[jj][0] = g.x * v0.x + g.y * v1.x + g.z * v2.x + g.w * v3.x;
                rr[jj][1] = g.x * v0.y + g.y * v1.y + g.z * v2.y + g.w * v3.y;
                rr[jj][2] = g.x * v0.z + g.y * v1.z + g.z * v2.z + g.w * v3.z;
                rr[jj][3] = g.x * v0.w + g.y * v1.w + g.z * v2.w + g.w * v3.w;
            }
            int chunk = (hg * 2 + j) ^ xorc;   // XOR-swizzled 16B chunk (4 px)
            #pragma unroll
            for (int q = 0; q < 4; q++) {
                *(float4*)(xoffb + ((lg * 4 + q) << 9) + (chunk << 4)) =
                    make_float4(rr[0][q], rr[1][q], rr[2][q], rr[3][q]);
            }
        }
        __syncthreads();

        // ---- phase 2: GEMM: acc[o=warp*8+r][px lane*4..+3] += w[o,k]*x[k,px] ----
        #pragma unroll 4
        for (int k = 0; k < 64; k++) {
            int xk = (k >> 2) & 7;
            ulonglong2 xA = *(const ulonglong2*)(xoffb + (k << 9) + ((lane ^ xk) << 4));
            const ULL* wr = ws2 + (k << 6) + (warp << 3);      // warp-uniform
            ulonglong2 w01 = *(const ulonglong2*)(wr + 0);
            ulonglong2 w23 = *(const ulonglong2*)(wr + 2);
            ulonglong2 w45 = *(const ulonglong2*)(wr + 4);
            ulonglong2 w67 = *(const ulonglong2*)(wr + 6);
            acc[0][0] = ffma2(xA.x, w01.x, acc[0][0]);
            acc[0][1] = ffma2(xA.y, w01.x, acc[0][1]);
            acc[1][0] = ffma2(xA.x, w01.y, acc[1][0]);
            acc[1][1] = ffma2(xA.y, w01.y, acc[1][1]);
            acc[2][0] = ffma2(xA.x, w23.x, acc[2][0]);
            acc[2][1] = ffma2(xA.y, w23.x, acc[2][1]);
            acc[3][0] = ffma2(xA.x, w23.y, acc[3][0]);
            acc[3][1] = ffma2(xA.y, w23.y, acc[3][1]);
            acc[4][0] = ffma2(xA.x, w45.x, acc[4][0]);
            acc[4][1] = ffma2(xA.y, w45.x, acc[4][1]);
            acc[5][0] = ffma2(xA.x, w45.y, acc[5][0]);
            acc[5][1] = ffma2(xA.y, w45.y, acc[5][1]);
            acc[6][0] = ffma2(xA.x, w67.x, acc[6][0]);
            acc[6][1] = ffma2(xA.y, w67.x, acc[6][1]);
            acc[7][0] = ffma2(xA.x, w67.y, acc[7][0]);
            acc[7][1] = ffma2(xA.y, w67.y, acc[7][1]);
        }
        __syncthreads();
    }

    // ---- write out: o = warp*8+r; px lane*4..+3 (coalesced) ----
    float* ob = out + ((b * O + warp * 8) * H + i) * W + lane * 4;
    #pragma unroll
    for (int r = 0; r < 8; r++) {
        float4 v;
        unpack2(acc[r][0], v.x, v.y);
        unpack2(acc[r][1], v.z, v.w);
        *(float4*)(ob + r * (H * W)) = v;
    }
}

// ============================================================================
extern "C" void kernel_launch(void* const* d_in, const int* in_sizes, int n_in,
                              void* d_out, int out_size) {
    const float* x0     = (const float*)d_in[0];
    const float* x1     = (const float*)d_in[1];
    const float* p_w    = (const float*)d_in[2];
    const float* p_b    = (const float*)d_in[3];
    const float* conv_w = (const float*)d_in[4];
    float* out = (float*)d_out;

    cudaFuncSetAttribute(k_main, cudaFuncAttributeMaxDynamicSharedMemorySize, SM_MAIN);
    cudaFuncSetAttribute(k_prep, cudaFuncAttributeMaxDynamicSharedMemorySize, PREP_SMEM);

    k_prep<<<NB_OFF + NB_PAD + NB_PW, 256, PREP_SMEM>>>(x0, x1, p_w, p_b, conv_w);
    k_main<<<B * H, 256, SM_MAIN>>>(out);
}